// round 2
// baseline (speedup 1.0000x reference)
#include <cuda_runtime.h>

#define M 8192
// scale = sqrt(HEAD_DIM) = sqrt(1024) = 32
#define LOG2E 1.4426950408889634f

// Scratch (no allocations allowed): q, k, v vectors + k min/max
__device__ float g_q[M];
__device__ float g_k[M];
__device__ float g_v[M];
__device__ float g_kmin_;
__device__ float g_kmax_;

__device__ __forceinline__ float ex2f(float x) {
    float y;
    asm("ex2.approx.ftz.f32 %0, %1;" : "=f"(y) : "f"(x));
    return y;
}

// ---------------------------------------------------------------------------
// Stage 1: q = Wq@x+bq, k = Wk@x+bk, v = Wv@x+bv
// Grid: 3 matrices x 1024 groups of 8 rows = 3072 blocks, 256 threads.
// x staged in smem once per block; W streamed from HBM (768 MB total).
// ---------------------------------------------------------------------------
__global__ __launch_bounds__(256) void qkv_kernel(
    const float* __restrict__ x,
    const float* __restrict__ Wq, const float* __restrict__ bq,
    const float* __restrict__ Wk, const float* __restrict__ bk,
    const float* __restrict__ Wv, const float* __restrict__ bv)
{
    __shared__ float4 xs[M / 4];   // 32 KB
    __shared__ float red[8];

    const int t = threadIdx.x;
    const int mat = blockIdx.x >> 10;       // 0,1,2
    const int group = blockIdx.x & 1023;    // 0..1023

    const float* W;
    const float* b;
    float* out;
    if (mat == 0)      { W = Wq; b = bq; out = g_q; }
    else if (mat == 1) { W = Wk; b = bk; out = g_k; }
    else               { W = Wv; b = bv; out = g_v; }

    const float4* x4 = (const float4*)x;
    #pragma unroll
    for (int i = 0; i < 8; i++) xs[t + i * 256] = x4[t + i * 256];
    __syncthreads();

    #pragma unroll 1
    for (int r = 0; r < 8; r++) {
        const int row = group * 8 + r;
        const float4* Wrow = (const float4*)(W + (size_t)row * M);

        float acc = 0.0f;
        #pragma unroll
        for (int s = 0; s < 8; s++) {
            float4 w  = Wrow[t + s * 256];
            float4 xv = xs[t + s * 256];
            acc += w.x * xv.x + w.y * xv.y + w.z * xv.z + w.w * xv.w;
        }

        // warp reduce
        #pragma unroll
        for (int o = 16; o > 0; o >>= 1)
            acc += __shfl_xor_sync(0xffffffffu, acc, o);
        if ((t & 31) == 0) red[t >> 5] = acc;
        __syncthreads();
        if (t == 0) {
            float s = 0.0f;
            #pragma unroll
            for (int w = 0; w < 8; w++) s += red[w];
            out[row] = s + b[row];
        }
        __syncthreads();
    }
}

// ---------------------------------------------------------------------------
// Stage 2: kmin / kmax of g_k (for softmax max-subtraction). One block.
// ---------------------------------------------------------------------------
__global__ __launch_bounds__(256) void kminmax_kernel()
{
    __shared__ float rmin[8], rmax[8];
    const int t = threadIdx.x;
    float mn = 1e30f, mx = -1e30f;
    #pragma unroll
    for (int i = 0; i < M / 256; i++) {
        float v = g_k[t + i * 256];
        mn = fminf(mn, v);
        mx = fmaxf(mx, v);
    }
    #pragma unroll
    for (int o = 16; o > 0; o >>= 1) {
        mn = fminf(mn, __shfl_xor_sync(0xffffffffu, mn, o));
        mx = fmaxf(mx, __shfl_xor_sync(0xffffffffu, mx, o));
    }
    if ((t & 31) == 0) { rmin[t >> 5] = mn; rmax[t >> 5] = mx; }
    __syncthreads();
    if (t == 0) {
        #pragma unroll
        for (int w = 1; w < 8; w++) {
            mn = fminf(mn, rmin[w]);
            mx = fmaxf(mx, rmax[w]);
        }
        g_kmin_ = mn;
        g_kmax_ = mx;
    }
}

// ---------------------------------------------------------------------------
// Stage 3: out[i] = sum_j exp(a_i*k_j - m_i) * v_j / sum_j exp(a_i*k_j - m_i)
// (everything in log2 domain so exp is a single MUFU.EX2)
// Grid: 1024 blocks x 256 threads; 8 rows per block so each (k_j, v_j) load
// feeds 8 exp evaluations -> MUFU-bound, ~16 exp/cyc/SM.
// ---------------------------------------------------------------------------
__global__ __launch_bounds__(256) void attn_kernel(float* __restrict__ out)
{
    __shared__ float redS[8], redT[8];

    const int t = threadIdx.x;
    const int base = blockIdx.x * 8;

    const float kmin = g_kmin_;
    const float kmax = g_kmax_;

    float a2[8], nm2[8], S[8], T[8];
    #pragma unroll
    for (int r = 0; r < 8; r++) {
        float a = g_q[base + r] * (LOG2E / 32.0f);      // log2-domain slope
        a2[r] = a;
        float m = (a >= 0.0f) ? a * kmax : a * kmin;    // row max (log2 domain)
        nm2[r] = -m;
        S[r] = 0.0f;
        T[r] = 0.0f;
    }

    const float4* k4 = (const float4*)g_k;
    const float4* v4 = (const float4*)g_v;

    #pragma unroll
    for (int s = 0; s < 8; s++) {
        const int idx = t + s * 256;
        float4 kq = k4[idx];
        float4 vq = v4[idx];
        #pragma unroll
        for (int c = 0; c < 4; c++) {
            float kc = (&kq.x)[c];
            float vc = (&vq.x)[c];
            #pragma unroll
            for (int r = 0; r < 8; r++) {
                float e = ex2f(fmaf(a2[r], kc, nm2[r]));
                S[r] += e;
                T[r] = fmaf(e, vc, T[r]);
            }
        }
    }

    // 8 block reductions of (S, T)
    #pragma unroll 1
    for (int r = 0; r < 8; r++) {
        float s = S[r], tt = T[r];
        #pragma unroll
        for (int o = 16; o > 0; o >>= 1) {
            s  += __shfl_xor_sync(0xffffffffu, s, o);
            tt += __shfl_xor_sync(0xffffffffu, tt, o);
        }
        if ((t & 31) == 0) { redS[t >> 5] = s; redT[t >> 5] = tt; }
        __syncthreads();
        if (t == 0) {
            float ss = 0.0f, st = 0.0f;
            #pragma unroll
            for (int w = 0; w < 8; w++) { ss += redS[w]; st += redT[w]; }
            out[base + r] = st / ss;
        }
        __syncthreads();
    }
}

// ---------------------------------------------------------------------------
extern "C" void kernel_launch(void* const* d_in, const int* in_sizes, int n_in,
                              void* d_out, int out_size)
{
    const float* x  = (const float*)d_in[0];
    const float* Wq = (const float*)d_in[1];
    const float* bq = (const float*)d_in[2];
    const float* Wk = (const float*)d_in[3];
    const float* bk = (const float*)d_in[4];
    const float* Wv = (const float*)d_in[5];
    const float* bv = (const float*)d_in[6];
    float* out = (float*)d_out;

    qkv_kernel<<<3072, 256>>>(x, Wq, bq, Wk, bk, Wv, bv);
    kminmax_kernel<<<1, 256>>>();
    attn_kernel<<<1024, 256>>>(out);
}